// round 9
// baseline (speedup 1.0000x reference)
#include <cuda_runtime.h>
#include <math.h>
#include <stdint.h>

#define BATCH 4
#define SEQ 2048
#define DMODEL 1024
#define DHEAD 64
#define SCALE 0.125f     // DH^-0.5

// Scratch (__device__ globals — allowed)
__device__ float g_proj[6][BATCH*SEQ*DHEAD];   // 0:Qu 1:Ku 2:Vu 3:Qc 4:Kc 5:Vc
__device__ float g_term1[BATCH][SEQ*SEQ];
__device__ float g_sig[BATCH][SEQ*SEQ];
__device__ float g_Su[BATCH][SEQ*SEQ];
__device__ float g_Sc[BATCH][SEQ*SEQ];

struct WPtrs { const float* w[6]; };

// ---------------------------------------------------------------------------
// tf32 helpers: hi/lo planes interleaved as uint2 (one LDS.64 per fragment reg)
// ---------------------------------------------------------------------------
__device__ __forceinline__ uint32_t f2tf32(float f) {
    uint32_t r;
    asm("cvt.rna.tf32.f32 %0, %1;" : "=r"(r) : "f"(f));
    return r;
}

__device__ __forceinline__ void split4(uint2* dst, float4 v) {
    float f[4] = {v.x, v.y, v.z, v.w};
    #pragma unroll
    for (int i = 0; i < 4; i++) {
        uint32_t h = f2tf32(f[i]);
        dst[i] = make_uint2(h, f2tf32(f[i] - __uint_as_float(h)));
    }
}

__device__ __forceinline__ void mma_tf32(float c[4],
                                         uint32_t a0, uint32_t a1, uint32_t a2, uint32_t a3,
                                         uint32_t b0, uint32_t b1) {
    asm volatile(
        "mma.sync.aligned.m16n8k8.row.col.f32.tf32.tf32.f32 "
        "{%0,%1,%2,%3}, {%4,%5,%6,%7}, {%8,%9}, {%0,%1,%2,%3};"
        : "+f"(c[0]), "+f"(c[1]), "+f"(c[2]), "+f"(c[3])
        : "r"(a0), "r"(a1), "r"(a2), "r"(a3), "r"(b0), "r"(b1));
}

// 3-term fp32-emulated mma from interleaved (hi,lo) fragments
__device__ __forceinline__ void mma3(float c[4], const uint2 a[4], uint2 b0, uint2 b1) {
    mma_tf32(c, a[0].x, a[1].x, a[2].x, a[3].x, b0.x, b1.x);
    mma_tf32(c, a[0].x, a[1].x, a[2].x, a[3].x, b0.y, b1.y);
    mma_tf32(c, a[0].y, a[1].y, a[2].y, a[3].y, b0.x, b1.x);
}

// ---------------------------------------------------------------------------
// Kernel 1: projections. out[row][n] = sum_d x[row][d] * w[d][n]
// 256 threads, tile 128(m) x 64(n), BK=16, 8 warps of 32x32.
// ---------------------------------------------------------------------------
__global__ __launch_bounds__(256, 2) void proj_mma_kernel(const float* __restrict__ x, WPtrs wp) {
    __shared__ uint2 As[128][20];   // [m][k] hi/lo interleaved, pad 4
    __shared__ uint2 Bs[64][20];    // [n][k]
    const float* __restrict__ w = wp.w[blockIdx.y];
    float* __restrict__ out = g_proj[blockIdx.y];
    const int tid = threadIdx.x;
    const int warp = tid >> 5, lane = tid & 31;
    const int g = lane >> 2, t = lane & 3;
    const int row0 = blockIdx.x * 128;
    const int wm = (warp >> 1) * 32, wn = (warp & 1) * 32;
    const int lr = tid >> 2, lc4 = (tid & 3) * 4;
    float acc[2][4][4] = {};
    for (int kc = 0; kc < DMODEL; kc += 16) {
        #pragma unroll
        for (int p = 0; p < 2; p++) {                 // A: 128x16
            int r = p * 64 + lr;
            float4 av = *(const float4*)&x[(size_t)(row0 + r) * DMODEL + kc + lc4];
            split4(&As[r][lc4], av);
        }
        {                                              // B: 16k x 64n -> [n][k]
            int kr = tid >> 4, n4 = (tid & 15) * 4;
            float4 wv = *(const float4*)&w[(size_t)(kc + kr) * DHEAD + n4];
            float f[4] = {wv.x, wv.y, wv.z, wv.w};
            #pragma unroll
            for (int i = 0; i < 4; i++) {
                uint32_t h = f2tf32(f[i]);
                Bs[n4 + i][kr] = make_uint2(h, f2tf32(f[i] - __uint_as_float(h)));
            }
        }
        __syncthreads();
        #pragma unroll
        for (int ks = 0; ks < 2; ks++) {
            const int ko = ks * 8;
            uint2 af[2][4];
            #pragma unroll
            for (int mt = 0; mt < 2; mt++) {
                int r0 = wm + mt * 16;
                af[mt][0] = As[r0 + g][ko + t];     af[mt][1] = As[r0 + g + 8][ko + t];
                af[mt][2] = As[r0 + g][ko + t + 4]; af[mt][3] = As[r0 + g + 8][ko + t + 4];
            }
            #pragma unroll
            for (int nt = 0; nt < 4; nt++) {
                int c0 = wn + nt * 8;
                uint2 b0 = Bs[c0 + g][ko + t], b1 = Bs[c0 + g][ko + t + 4];
                #pragma unroll
                for (int mt = 0; mt < 2; mt++) mma3(acc[mt][nt], af[mt], b0, b1);
            }
        }
        __syncthreads();
    }
    #pragma unroll
    for (int mt = 0; mt < 2; mt++) {
        const int gi0 = row0 + wm + mt * 16 + g;
        #pragma unroll
        for (int nt = 0; nt < 4; nt++) {
            const int gj = wn + nt * 8 + 2 * t;
            *(float2*)&out[(size_t)gi0 * DHEAD + gj] =
                make_float2(acc[mt][nt][0], acc[mt][nt][1]);
            *(float2*)&out[(size_t)(gi0 + 8) * DHEAD + gj] =
                make_float2(acc[mt][nt][2], acc[mt][nt][3]);
        }
    }
}

// ---------------------------------------------------------------------------
// Unified NT GEMM: C[i][j] = <Arow i, Brow j>. 256 threads, 128x128 block,
// 8 warps of 32(m)x64(n), BK=16.
// OP 0: term1 = (j<=i)? v*scale : 0            A=Qc B=Vu  K=64  (lower)
// OP 1: S_c   = (j<=i)? v*scale : -inf         A=Qc B=Kc  K=64  (lower)
// OP 2: sig   = (j>k)?  sigmoid(v*scale) : 0   A=Qu B=Ku  K=64  (upper)
// OP 3: S_u   = v                              A=term1 B=sig, K=[j0, i0+128)
// ---------------------------------------------------------------------------
template <int OP>
__global__ __launch_bounds__(256, 2) void mma_nt_kernel() {
    const int tiB = blockIdx.x, tjB = blockIdx.y, b = blockIdx.z;
    if (OP == 2) { if (tjB < tiB) return; } else { if (tjB > tiB) return; }
    const int i0 = tiB * 128, j0 = tjB * 128;

    const float* __restrict__ Ab;
    const float* __restrict__ Bb;
    float* __restrict__ Cb;
    size_t lda;
    int kbeg, kend;
    if (OP == 0)      { Ab = g_proj[3] + b*SEQ*DHEAD; Bb = g_proj[2] + b*SEQ*DHEAD; Cb = g_term1[b]; lda = DHEAD; kbeg = 0;  kend = DHEAD; }
    else if (OP == 1) { Ab = g_proj[3] + b*SEQ*DHEAD; Bb = g_proj[4] + b*SEQ*DHEAD; Cb = g_Sc[b];    lda = DHEAD; kbeg = 0;  kend = DHEAD; }
    else if (OP == 2) { Ab = g_proj[0] + b*SEQ*DHEAD; Bb = g_proj[1] + b*SEQ*DHEAD; Cb = g_sig[b];   lda = DHEAD; kbeg = 0;  kend = DHEAD; }
    else              { Ab = g_term1[b];              Bb = g_sig[b];                Cb = g_Su[b];    lda = SEQ;   kbeg = j0; kend = i0 + 128; }

    __shared__ uint2 As[128][20];   // hi/lo interleaved
    __shared__ uint2 Bs[128][20];

    const int tid = threadIdx.x;
    const int warp = tid >> 5, lane = tid & 31;
    const int g = lane >> 2, t = lane & 3;
    const int wm = (warp >> 1) * 32, wn = (warp & 1) * 64;
    const int lr = tid >> 2, lc4 = (tid & 3) * 4;
    float acc[2][8][4] = {};

    for (int kc = kbeg; kc < kend; kc += 16) {
        #pragma unroll
        for (int p = 0; p < 2; p++) {                  // A and B: 128x16 each
            int r = p * 64 + lr;
            float4 av = *(const float4*)&Ab[(size_t)(i0 + r) * lda + kc + lc4];
            split4(&As[r][lc4], av);
            float4 bv = *(const float4*)&Bb[(size_t)(j0 + r) * lda + kc + lc4];
            split4(&Bs[r][lc4], bv);
        }
        __syncthreads();
        #pragma unroll
        for (int ks = 0; ks < 2; ks++) {
            const int ko = ks * 8;
            uint2 af[2][4];
            #pragma unroll
            for (int mt = 0; mt < 2; mt++) {
                int r0 = wm + mt * 16;
                af[mt][0] = As[r0 + g][ko + t];     af[mt][1] = As[r0 + g + 8][ko + t];
                af[mt][2] = As[r0 + g][ko + t + 4]; af[mt][3] = As[r0 + g + 8][ko + t + 4];
            }
            #pragma unroll
            for (int nt = 0; nt < 8; nt++) {
                int c0 = wn + nt * 8;
                uint2 b0 = Bs[c0 + g][ko + t], b1 = Bs[c0 + g][ko + t + 4];
                #pragma unroll
                for (int mt = 0; mt < 2; mt++) mma3(acc[mt][nt], af[mt], b0, b1);
            }
        }
        __syncthreads();
    }

    // Epilogue
    #pragma unroll
    for (int mt = 0; mt < 2; mt++) {
        const int gi0 = i0 + wm + mt * 16 + g;
        #pragma unroll
        for (int nt = 0; nt < 8; nt++) {
            const int gj = j0 + wn + nt * 8 + 2 * t;
            float v[4] = {acc[mt][nt][0], acc[mt][nt][1], acc[mt][nt][2], acc[mt][nt][3]};
            float o[4];
            #pragma unroll
            for (int e = 0; e < 4; e++) {
                const int gi = gi0 + (e >> 1) * 8;
                const int gjj = gj + (e & 1);
                if (OP == 0)      o[e] = (gjj <= gi) ? v[e] * SCALE : 0.0f;
                else if (OP == 1) o[e] = (gjj <= gi) ? v[e] * SCALE : -INFINITY;
                else if (OP == 2) o[e] = (gjj > gi) ? 1.0f / (1.0f + __expf(-v[e] * SCALE)) : 0.0f;
                else              o[e] = v[e];
            }
            *(float2*)&Cb[(size_t)gi0 * SEQ + gj]       = make_float2(o[0], o[1]);
            *(float2*)&Cb[(size_t)(gi0 + 8) * SEQ + gj] = make_float2(o[2], o[3]);
        }
    }
}

// ---------------------------------------------------------------------------
// Kernel 4: fused online softmax + attn @ V_c (unchanged).
// One block per (b, 32-row i-tile), 256 threads: r=tid/8 (row), q=tid%8.
// ---------------------------------------------------------------------------
__global__ __launch_bounds__(256) void softmax_av_kernel(float* __restrict__ out) {
    const int t32 = blockIdx.x, b = blockIdx.y;
    __shared__ float Ls[32][65];
    __shared__ float Vs[64][64];
    const float* __restrict__ sc = g_Sc[b];
    const float* __restrict__ su = g_Su[b];
    const float* __restrict__ Vc = g_proj[5] + b * SEQ * DHEAD;
    const int tid = threadIdx.x;
    const int i0 = t32 * 32;
    const int r = tid >> 3, q = tid & 7, d0 = q * 8;
    const int njt = (t32 >> 1) + 1;     // 64-wide j tiles covering j<=i
    float m_prev = -INFINITY, Z = 0.0f;
    float acc[8] = {};
    for (int tj = 0; tj < njt; tj++) {
        const int j0 = tj * 64;
        __syncthreads();
        #pragma unroll
        for (int l = 0; l < 4; l++) {
            int idx = tid + l * 256;
            int rr = idx >> 4, cg = idx & 15;
            *(float4*)&Vs[rr][cg*4] = *(const float4*)&Vc[(j0 + rr) * DHEAD + cg * 4];
        }
        #pragma unroll
        for (int l = 0; l < 8; l++) {
            int idx = tid + l * 256;
            int rr = idx >> 6, cc = idx & 63;
            int gi = i0 + rr, gj = j0 + cc;
            float lv;
            if (gj > gi) {
                lv = -INFINITY;
            } else {
                float s = su[(size_t)gi * SEQ + gj];
                float sil = s / (1.0f + __expf(-s));
                lv = sc[(size_t)gi * SEQ + gj] - sil;
            }
            Ls[rr][cc] = lv;
        }
        __syncthreads();
        float mt = -INFINITY;
        #pragma unroll
        for (int c = 0; c < 8; c++) mt = fmaxf(mt, Ls[r][d0 + c]);
        mt = fmaxf(mt, __shfl_xor_sync(0xffffffffu, mt, 1));
        mt = fmaxf(mt, __shfl_xor_sync(0xffffffffu, mt, 2));
        mt = fmaxf(mt, __shfl_xor_sync(0xffffffffu, mt, 4));
        float m_new = fmaxf(m_prev, mt);
        float scl = __expf(m_prev - m_new);
        float zl = 0.0f;
        #pragma unroll
        for (int c = 0; c < 8; c++) {
            float p = __expf(Ls[r][d0 + c] - m_new);
            Ls[r][d0 + c] = p;
            zl += p;
        }
        zl += __shfl_xor_sync(0xffffffffu, zl, 1);
        zl += __shfl_xor_sync(0xffffffffu, zl, 2);
        zl += __shfl_xor_sync(0xffffffffu, zl, 4);
        Z = Z * scl + zl;
        m_prev = m_new;
        #pragma unroll
        for (int d = 0; d < 8; d++) acc[d] *= scl;
        __syncwarp();
        #pragma unroll 8
        for (int c = 0; c < 64; c++) {
            float p = Ls[r][c];
            float v[8];
            *(float4*)&v[0] = *(const float4*)&Vs[c][d0];
            *(float4*)&v[4] = *(const float4*)&Vs[c][d0 + 4];
            #pragma unroll
            for (int d = 0; d < 8; d++) acc[d] += p * v[d];
        }
    }
    const float inv = 1.0f / Z;
    const int gi = i0 + r;
    float* op = &out[((size_t)(b * SEQ + gi)) * DHEAD + d0];
    *(float4*)&op[0] = make_float4(acc[0]*inv, acc[1]*inv, acc[2]*inv, acc[3]*inv);
    *(float4*)&op[4] = make_float4(acc[4]*inv, acc[5]*inv, acc[6]*inv, acc[7]*inv);
}

// ---------------------------------------------------------------------------
extern "C" void kernel_launch(void* const* d_in, const int* in_sizes, int n_in,
                              void* d_out, int out_size) {
    const float* x = (const float*)d_in[0];
    WPtrs wp;
    for (int i = 0; i < 6; i++) wp.w[i] = (const float*)d_in[1 + i];

    dim3 g1((BATCH * SEQ) / 128, 6);
    proj_mma_kernel<<<g1, 256>>>(x, wp);

    dim3 g2(SEQ / 128, SEQ / 128, BATCH);
    mma_nt_kernel<0><<<g2, 256>>>();   // term1 = Qc.Vu^T (lower)
    mma_nt_kernel<1><<<g2, 256>>>();   // S_c   = Qc.Kc^T (lower)
    mma_nt_kernel<2><<<g2, 256>>>();   // sig   = sigmoid(Qu.Ku^T) (upper)
    mma_nt_kernel<3><<<g2, 256>>>();   // S_u   = term1 . sig^T (triangular K)

    dim3 g4(SEQ / 32, BATCH);
    softmax_av_kernel<<<g4, 256>>>((float*)d_out);
}